// round 9
// baseline (speedup 1.0000x reference)
#include <cuda_runtime.h>

// Gaussian-splat render, round 6.
//   out[n,c] = sum_m exp(-0.5 * d^T C_m^-1 d) * cols[m,c]
//
// R4 (71.9us): P=4, 16 warps/SM, fma 55.7% — stall-bound on co-saturated
//   FMA+MUFU pipes with only 4 warps/SMSP.
// R5 (75.8us): P=8 hit the 128-reg RF wall -> regression. RF is the binder.
// R6: P=4 state (40 persistent regs, Horner) at BLK=1024 under
//   __launch_bounds__(1024,1) (64-reg budget) -> 32 warps/SM, 8/SMSP.
//   Q=16 warp-aligned Gaussian slices of 128; same dup'd f32x2 table.

typedef unsigned long long u64;

static constexpr int N_GAUSS = 2048;
static constexpr int N_PAIR  = 32768;        // 65536 pixels / 2
static constexpr int P       = 4;            // pairs per thread
static constexpr int Q       = 16;           // Gaussian slices
static constexpr int GQ      = N_GAUSS / Q;  // 128 per thread
static constexpr int NSLOT   = N_PAIR / P;   // 8192 pair-slots
static constexpr int SPB     = 64;           // slots per CTA
static constexpr int BLK     = SPB * Q;      // 1024 threads
static constexpr int GRID    = 148;
static constexpr int SLOTS   = 10;           // u64 per Gaussian (5 x LDS.128)
static constexpr size_t SMEM_BYTES = (size_t)N_GAUSS * SLOTS * sizeof(u64); // 160KB

__device__ u64 g_tab[N_GAUSS * SLOTS];

__device__ __forceinline__ u64 pack2(float lo, float hi) {
    u64 r; asm("mov.b64 %0, {%1, %2};" : "=l"(r) : "f"(lo), "f"(hi)); return r;
}
__device__ __forceinline__ void unpack2(u64 v, float& lo, float& hi) {
    asm("mov.b64 {%0, %1}, %2;" : "=f"(lo), "=f"(hi) : "l"(v));
}
__device__ __forceinline__ u64 fma2(u64 a, u64 b, u64 c) {
    u64 d; asm("fma.rn.f32x2 %0, %1, %2, %3;" : "=l"(d) : "l"(a), "l"(b), "l"(c)); return d;
}
__device__ __forceinline__ float ex2f(float v) {
    float r; asm("ex2.approx.f32 %0, %1;" : "=f"(r) : "f"(v)); return r;
}

// ---- Prep: per-Gaussian coefficient + color table (lane-duplicated) ----
__global__ void prep_kernel(const float* __restrict__ mus,
                            const float* __restrict__ covs,
                            const float* __restrict__ cols)
{
    int m = blockIdx.x * blockDim.x + threadIdx.x;
    if (m >= N_GAUSS) return;

    const float s = -0.72134752044448170368f;  // -0.5 * log2(e)
    float2 mu = ((const float2*)mus)[m];
    float4 cv = ((const float4*)covs)[m];      // [a, b, b, c]
    float a = cv.x, b = cv.y, c = cv.w;
    float inv_det = 1.0f / (a * c - b * b);
    float p00 =  c * inv_det;
    float p01 = -b * inv_det;
    float p11 =  a * inv_det;

    float cxx = s * p00;
    float cxy = s * (2.0f * p01);
    float cyy = s * p11;
    float l1 = p00 * mu.x + p01 * mu.y;
    float l2 = p01 * mu.x + p11 * mu.y;
    float cx = s * (-2.0f * l1);
    float cy = s * (-2.0f * l2);
    float c0 = s * (mu.x * l1 + mu.y * l2);

    float r  = cols[3 * m + 0];
    float g  = cols[3 * m + 1];
    float bl = cols[3 * m + 2];

    u64* q = g_tab + (size_t)m * SLOTS;
    q[0] = pack2(cxx, cxx);
    q[1] = pack2(cxy, cxy);
    q[2] = pack2(cyy, cyy);
    q[3] = pack2(cx,  cx);
    q[4] = pack2(cy,  cy);
    q[5] = pack2(c0,  c0);
    q[6] = pack2(r,   r);
    q[7] = pack2(g,   g);
    q[8] = pack2(bl,  bl);
    q[9] = 0ull;
}

// ---- Main render ----
__global__ __launch_bounds__(BLK, 1)
void render_kernel(const float* __restrict__ x, float* __restrict__ out)
{
    extern __shared__ u64 sh[];
    const int tid = threadIdx.x;

    // bulk copy table into shared
    {
        const ulonglong2* src = (const ulonglong2*)g_tab;
        ulonglong2* dst = (ulonglong2*)sh;
        #pragma unroll 4
        for (int i = tid; i < N_GAUSS * SLOTS / 2; i += BLK) dst[i] = src[i];
    }
    __syncthreads();

    const int slice = tid >> 6;                   // 0..15, 2 warps per slice
    const int slot  = tid & (SPB - 1);            // 0..63
    const int sg    = blockIdx.x + GRID * slot;   // round-robin pair-slot
    const bool active = (sg < NSLOT);

    u64 X1[P], X2[P];
    u64 aR[P], aG[P], aB[P];

    if (active) {
        #pragma unroll
        for (int i = 0; i < P; ++i) {
            float4 xv = ((const float4*)x)[sg + NSLOT * i];
            X1[i] = pack2(xv.x, xv.z);
            X2[i] = pack2(xv.y, xv.w);
            aR[i] = 0ull; aG[i] = 0ull; aB[i] = 0ull;
        }

        const ulonglong2* S = (const ulonglong2*)sh;   // 5 x LDS.128 per Gaussian
        const int mbase = slice * GQ;

        #pragma unroll 2
        for (int j = 0; j < GQ; ++j) {
            const int m = mbase + j;
            ulonglong2 v0 = S[m * 5 + 0];  // {cxx} {cxy}
            ulonglong2 v1 = S[m * 5 + 1];  // {cyy} {cx }
            ulonglong2 v2 = S[m * 5 + 2];  // {cy } {c0 }
            ulonglong2 v3 = S[m * 5 + 3];  // {r  } {g  }
            ulonglong2 v4 = S[m * 5 + 4];  // {b  } {pad}

            #pragma unroll
            for (int i = 0; i < P; ++i) {
                // Horner: t = x*(cxx*x + cxy*y + cx) + (y*(cyy*y + cy) + c0)
                u64 u = fma2(v0.y, X2[i], v1.y);   // cxy*y + cx
                u     = fma2(v0.x, X1[i], u);      // + cxx*x
                u64 v = fma2(v1.x, X2[i], v2.x);   // cyy*y + cy
                u64 t = fma2(X2[i], v, v2.y);      // y*(..) + c0
                t     = fma2(X1[i], u, t);         // + x*(..)

                float tl, th;
                unpack2(t, tl, th);
                u64 w = pack2(ex2f(tl), ex2f(th));

                aR[i] = fma2(v3.x, w, aR[i]);
                aG[i] = fma2(v3.y, w, aG[i]);
                aB[i] = fma2(v4.x, w, aB[i]);
            }
        }
    }

    // ---- cross-slice reduction via shared (reuse coeff region) ----
    __syncthreads();                  // all reads of S done
    float* red = (float*)sh;          // [Q-1][SPB][P][6] = 90KB
    if (slice != 0 && active) {
        float* qp = red + (((slice - 1) * SPB + slot) * P) * 6;
        #pragma unroll
        for (int i = 0; i < P; ++i) {
            float r0, r1, g0, g1, b0, b1;
            unpack2(aR[i], r0, r1);
            unpack2(aG[i], g0, g1);
            unpack2(aB[i], b0, b1);
            float* qq = qp + i * 6;
            qq[0] = r0; qq[1] = r1; qq[2] = g0; qq[3] = g1; qq[4] = b0; qq[5] = b1;
        }
    }
    __syncthreads();
    if (slice == 0 && active) {
        #pragma unroll
        for (int i = 0; i < P; ++i) {
            float r0, r1, g0, g1, b0, b1;
            unpack2(aR[i], r0, r1);
            unpack2(aG[i], g0, g1);
            unpack2(aB[i], b0, b1);
            for (int qd = 0; qd < Q - 1; ++qd) {
                const float* qq = red + (((qd * SPB + slot) * P) + i) * 6;
                r0 += qq[0]; r1 += qq[1];
                g0 += qq[2]; g1 += qq[3];
                b0 += qq[4]; b1 += qq[5];
            }
            const int p = sg + NSLOT * i;        // pair index
            float2* o = (float2*)(out + (size_t)p * 6);
            o[0] = make_float2(r0, g0);
            o[1] = make_float2(b0, r1);
            o[2] = make_float2(g1, b1);
        }
    }
}

extern "C" void kernel_launch(void* const* d_in, const int* in_sizes, int n_in,
                              void* d_out, int out_size)
{
    const float* x    = (const float*)d_in[0];
    const float* mus  = (const float*)d_in[1];
    const float* covs = (const float*)d_in[2];
    const float* cols = (const float*)d_in[3];
    float* out = (float*)d_out;

    prep_kernel<<<(N_GAUSS + 255) / 256, 256>>>(mus, covs, cols);

    cudaFuncSetAttribute(render_kernel,
                         cudaFuncAttributeMaxDynamicSharedMemorySize,
                         (int)SMEM_BYTES);
    render_kernel<<<GRID, BLK, SMEM_BYTES>>>(x, out);
}

// round 10
// speedup vs baseline: 1.2666x; 1.2666x over previous
#include <cuda_runtime.h>
#include <cuda_fp16.h>

// Gaussian-splat render, round 7.
//   out[n,c] = sum_m exp(-0.5 * d^T C_m^-1 d) * cols[m,c]
//
// Findings: fma caps ~55% independent of occupancy (R4 16w/SM = R6 32w/SM);
// runtime fits FMA-pipe-cycles + MUFU-cycles (additive). So: remove pipe work.
// R7 = R4 structure (P=4 pairs/thread, Q=8 slices, BLK=512) with:
//  * ONE ex2.approx.f16x2 per pair-G (was two ex2.approx.f32) -> MUFU halved.
//  * Color accumulation in HFMA2 (f16x2), f32 flush every 8 Gaussians
//    (validated numerically in R2: rel_err 3.7e-4).
//  * Table now 4 x LDS.128 per Gaussian (6 f32x2 coeffs + packed half2 RGB).

typedef unsigned long long u64;

static constexpr int N_GAUSS = 2048;
static constexpr int N_PAIR  = 32768;        // 65536 pixels / 2
static constexpr int P       = 4;            // pairs per thread
static constexpr int Q       = 8;            // Gaussian slices
static constexpr int GQ      = N_GAUSS / Q;  // 256 per thread
static constexpr int NSLOT   = N_PAIR / P;   // 8192 pair-slots
static constexpr int SPB     = 64;           // slots per CTA (warp-aligned)
static constexpr int BLK     = SPB * Q;      // 512 threads
static constexpr int GRID    = 148;
static constexpr int SLOTS   = 8;            // u64 per Gaussian (4 x LDS.128)
static constexpr size_t SMEM_BYTES = (size_t)N_GAUSS * SLOTS * sizeof(u64); // 128KB

__device__ u64 g_tab[N_GAUSS * SLOTS];

__device__ __forceinline__ u64 pack2(float lo, float hi) {
    u64 r; asm("mov.b64 %0, {%1, %2};" : "=l"(r) : "f"(lo), "f"(hi)); return r;
}
__device__ __forceinline__ u64 fma2(u64 a, u64 b, u64 c) {
    u64 d; asm("fma.rn.f32x2 %0, %1, %2, %3;" : "=l"(d) : "l"(a), "l"(b), "l"(c)); return d;
}
// f32x2 -> f16x2 (lane order preserved: lo f32 -> lo half)
__device__ __forceinline__ unsigned cvt_h2(u64 t) {
    float lo, hi; unsigned r;
    asm("mov.b64 {%0, %1}, %2;" : "=f"(lo), "=f"(hi) : "l"(t));
    asm("cvt.rn.f16x2.f32 %0, %1, %2;" : "=r"(r) : "f"(hi), "f"(lo));
    return r;
}
__device__ __forceinline__ unsigned ex2_h2(unsigned v) {
    unsigned r; asm("ex2.approx.f16x2 %0, %1;" : "=r"(r) : "r"(v)); return r;
}
__device__ __forceinline__ unsigned hfma2(unsigned a, unsigned b, unsigned c) {
    unsigned d; asm("fma.rn.f16x2 %0, %1, %2, %3;" : "=r"(d) : "r"(a), "r"(b), "r"(c)); return d;
}
__device__ __forceinline__ float2 h2f(unsigned v) {
    __half2 h = *reinterpret_cast<__half2*>(&v);
    return __half22float2(h);
}

// ---- Prep: per-Gaussian coefficient + color table ----
__global__ void prep_kernel(const float* __restrict__ mus,
                            const float* __restrict__ covs,
                            const float* __restrict__ cols)
{
    int m = blockIdx.x * blockDim.x + threadIdx.x;
    if (m >= N_GAUSS) return;

    const float s = -0.72134752044448170368f;  // -0.5 * log2(e)
    float2 mu = ((const float2*)mus)[m];
    float4 cv = ((const float4*)covs)[m];      // [a, b, b, c]
    float a = cv.x, b = cv.y, c = cv.w;
    float inv_det = 1.0f / (a * c - b * b);
    float p00 =  c * inv_det;
    float p01 = -b * inv_det;
    float p11 =  a * inv_det;

    float cxx = s * p00;
    float cxy = s * (2.0f * p01);
    float cyy = s * p11;
    float l1 = p00 * mu.x + p01 * mu.y;
    float l2 = p01 * mu.x + p11 * mu.y;
    float cx = s * (-2.0f * l1);
    float cy = s * (-2.0f * l2);
    float c0 = s * (mu.x * l1 + mu.y * l2);

    float r  = cols[3 * m + 0];
    float g  = cols[3 * m + 1];
    float bl = cols[3 * m + 2];

    u64* q = g_tab + (size_t)m * SLOTS;
    q[0] = pack2(cxx, cxx);
    q[1] = pack2(cxy, cxy);
    q[2] = pack2(cyy, cyy);
    q[3] = pack2(cx,  cx);
    q[4] = pack2(cy,  cy);
    q[5] = pack2(c0,  c0);
    // colors as lane-duplicated half2: {r,r} {g,g} in q[6], {b,b} pad in q[7]
    __half2 hr = __floats2half2_rn(r,  r);
    __half2 hg = __floats2half2_rn(g,  g);
    __half2 hb = __floats2half2_rn(bl, bl);
    unsigned ur = *reinterpret_cast<unsigned*>(&hr);
    unsigned ug = *reinterpret_cast<unsigned*>(&hg);
    unsigned ub = *reinterpret_cast<unsigned*>(&hb);
    q[6] = ((u64)ug << 32) | ur;
    q[7] = (u64)ub;
}

// ---- Main render ----
__global__ __launch_bounds__(BLK, 1)
void render_kernel(const float* __restrict__ x, float* __restrict__ out)
{
    extern __shared__ u64 sh[];
    const int tid = threadIdx.x;

    // bulk copy table into shared
    {
        const ulonglong2* src = (const ulonglong2*)g_tab;
        ulonglong2* dst = (ulonglong2*)sh;
        #pragma unroll 4
        for (int i = tid; i < N_GAUSS * SLOTS / 2; i += BLK) dst[i] = src[i];
    }
    __syncthreads();

    const int slice = tid >> 6;                   // 0..7, 2 warps per slice
    const int slot  = tid & (SPB - 1);            // 0..63
    const int sg    = blockIdx.x + GRID * slot;   // round-robin pair-slot
    const bool active = (sg < NSLOT);

    u64 X1[P], X2[P];
    float aR0[P], aR1[P], aG0[P], aG1[P], aB0[P], aB1[P];

    if (active) {
        #pragma unroll
        for (int i = 0; i < P; ++i) {
            float4 xv = ((const float4*)x)[sg + NSLOT * i];
            X1[i] = pack2(xv.x, xv.z);
            X2[i] = pack2(xv.y, xv.w);
            aR0[i] = aR1[i] = aG0[i] = aG1[i] = aB0[i] = aB1[i] = 0.f;
        }

        const ulonglong2* S = (const ulonglong2*)sh;   // 4 x LDS.128 per Gaussian
        const int mbase = slice * GQ;

        for (int blk = 0; blk < GQ / 8; ++blk) {
            unsigned hR[P], hG[P], hB[P];
            #pragma unroll
            for (int i = 0; i < P; ++i) { hR[i] = 0u; hG[i] = 0u; hB[i] = 0u; }

            #pragma unroll
            for (int j = 0; j < 8; ++j) {
                const int m = mbase + blk * 8 + j;
                ulonglong2 v0 = S[m * 4 + 0];  // {cxx} {cxy}
                ulonglong2 v1 = S[m * 4 + 1];  // {cyy} {cx }
                ulonglong2 v2 = S[m * 4 + 2];  // {cy } {c0 }
                ulonglong2 v3 = S[m * 4 + 3];  // {h2r,h2g} {h2b,pad}
                unsigned cr = (unsigned)(v3.x);
                unsigned cg = (unsigned)(v3.x >> 32);
                unsigned cb = (unsigned)(v3.y);

                #pragma unroll
                for (int i = 0; i < P; ++i) {
                    // Horner: t = x*(cxx*x + cxy*y + cx) + (y*(cyy*y + cy) + c0)
                    u64 u = fma2(v0.y, X2[i], v1.y);
                    u     = fma2(v0.x, X1[i], u);
                    u64 v = fma2(v1.x, X2[i], v2.x);
                    u64 t = fma2(X2[i], v, v2.y);
                    t     = fma2(X1[i], u, t);

                    unsigned w = ex2_h2(cvt_h2(t));   // one MUFU per pair
                    hR[i] = hfma2(cr, w, hR[i]);
                    hG[i] = hfma2(cg, w, hG[i]);
                    hB[i] = hfma2(cb, w, hB[i]);
                }
            }
            #pragma unroll
            for (int i = 0; i < P; ++i) {
                float2 fr = h2f(hR[i]); aR0[i] += fr.x; aR1[i] += fr.y;
                float2 fg = h2f(hG[i]); aG0[i] += fg.x; aG1[i] += fg.y;
                float2 fb = h2f(hB[i]); aB0[i] += fb.x; aB1[i] += fb.y;
            }
        }
    }

    // ---- cross-slice reduction via shared (reuse coeff region) ----
    __syncthreads();                  // all reads of S done
    float* red = (float*)sh;          // [Q-1][SPB][P][6] = 43KB
    if (slice != 0 && active) {
        float* qp = red + (((slice - 1) * SPB + slot) * P) * 6;
        #pragma unroll
        for (int i = 0; i < P; ++i) {
            float* qq = qp + i * 6;
            qq[0] = aR0[i]; qq[1] = aR1[i];
            qq[2] = aG0[i]; qq[3] = aG1[i];
            qq[4] = aB0[i]; qq[5] = aB1[i];
        }
    }
    __syncthreads();
    if (slice == 0 && active) {
        #pragma unroll
        for (int i = 0; i < P; ++i) {
            float r0 = aR0[i], r1 = aR1[i];
            float g0 = aG0[i], g1 = aG1[i];
            float b0 = aB0[i], b1 = aB1[i];
            for (int qd = 0; qd < Q - 1; ++qd) {
                const float* qq = red + (((qd * SPB + slot) * P) + i) * 6;
                r0 += qq[0]; r1 += qq[1];
                g0 += qq[2]; g1 += qq[3];
                b0 += qq[4]; b1 += qq[5];
            }
            const int p = sg + NSLOT * i;        // pair index
            float2* o = (float2*)(out + (size_t)p * 6);
            o[0] = make_float2(r0, g0);
            o[1] = make_float2(b0, r1);
            o[2] = make_float2(g1, b1);
        }
    }
}

extern "C" void kernel_launch(void* const* d_in, const int* in_sizes, int n_in,
                              void* d_out, int out_size)
{
    const float* x    = (const float*)d_in[0];
    const float* mus  = (const float*)d_in[1];
    const float* covs = (const float*)d_in[2];
    const float* cols = (const float*)d_in[3];
    float* out = (float*)d_out;

    prep_kernel<<<(N_GAUSS + 255) / 256, 256>>>(mus, covs, cols);

    cudaFuncSetAttribute(render_kernel,
                         cudaFuncAttributeMaxDynamicSharedMemorySize,
                         (int)SMEM_BYTES);
    render_kernel<<<GRID, BLK, SMEM_BYTES>>>(x, out);
}

// round 11
// speedup vs baseline: 1.6005x; 1.2636x over previous
#include <cuda_runtime.h>
#include <cuda_fp16.h>

// Gaussian-splat render, round 8.
//   out[n,c] = sum_m exp(-0.5 * d^T C_m^-1 d) * cols[m,c]
//
// Cycle-model finding (fits R4-R7 to <3%): fma.rn.f32x2 runs at rt4
// (no packed speedup; issue-slot savings only), HFMA2 runs at rt2
// (true 2-wide). So move the quadratic to fp16 via Cholesky:
//   k*C^-1 = R^T R  =>  t = -[(r11*x + r12*y + m1)^2 + (r22*y + m2)^2]
// Sum of squares -> no catastrophic cancellation in fp16.
// Hot loop per pair-G: 5 f16 quad ops + 3 f16 color FMA = 8 fma-pipe ops
// (16 cyc) vs 26 in R7; negate via XOR (alu pipe); one ex2.approx.f16x2.
// Table: 8 half2 per Gaussian = 2 x LDS.128 (64KB smem).

typedef unsigned long long u64;

static constexpr int N_GAUSS = 2048;
static constexpr int N_PAIR  = 32768;        // 65536 pixels / 2
static constexpr int P       = 4;            // pairs per thread
static constexpr int Q       = 8;            // Gaussian slices
static constexpr int GQ      = N_GAUSS / Q;  // 256 per thread
static constexpr int NSLOT   = N_PAIR / P;   // 8192 pair-slots
static constexpr int SPB     = 64;           // slots per CTA (warp-aligned)
static constexpr int BLK     = SPB * Q;      // 512 threads
static constexpr int GRID    = 148;
static constexpr int SLOTS   = 4;            // u64 per Gaussian (2 x LDS.128)
static constexpr size_t SMEM_BYTES = (size_t)N_GAUSS * SLOTS * sizeof(u64); // 64KB

__device__ u64 g_tab[N_GAUSS * SLOTS];

__device__ __forceinline__ unsigned h2u(__half2 h) {
    return *reinterpret_cast<unsigned*>(&h);
}
__device__ __forceinline__ __half2 u2h(unsigned u) {
    return *reinterpret_cast<__half2*>(&u);
}
__device__ __forceinline__ unsigned ex2_h2(unsigned v) {
    unsigned r; asm("ex2.approx.f16x2 %0, %1;" : "=r"(r) : "r"(v)); return r;
}

// ---- Prep: per-Gaussian Cholesky table ----
__global__ void prep_kernel(const float* __restrict__ mus,
                            const float* __restrict__ covs,
                            const float* __restrict__ cols)
{
    int m = blockIdx.x * blockDim.x + threadIdx.x;
    if (m >= N_GAUSS) return;

    const float k = 0.72134752044448170368f;   // 0.5 * log2(e)
    float2 mu = ((const float2*)mus)[m];
    float4 cv = ((const float4*)covs)[m];      // [a, b, b, c]
    float a = cv.x, b = cv.y, c = cv.w;
    float inv_det = 1.0f / (a * c - b * b);
    float p00 =  c * inv_det * k;
    float p01 = -b * inv_det * k;
    float p11 =  a * inv_det * k;

    // Cholesky of scaled precision: [p00 p01; p01 p11] = R^T R
    float r11 = sqrtf(p00);
    float r12 = p01 / r11;
    float r22 = sqrtf(fmaxf(p11 - r12 * r12, 0.f));
    float m1  = -(r11 * mu.x + r12 * mu.y);
    float m2  = -(r22 * mu.y);

    float cr = cols[3 * m + 0];
    float cg = cols[3 * m + 1];
    float cb = cols[3 * m + 2];

    // lane-duplicated half2 values
    unsigned ur11 = h2u(__floats2half2_rn(r11, r11));
    unsigned ur12 = h2u(__floats2half2_rn(r12, r12));
    unsigned ur22 = h2u(__floats2half2_rn(r22, r22));
    unsigned um1  = h2u(__floats2half2_rn(m1,  m1));
    unsigned um2  = h2u(__floats2half2_rn(m2,  m2));
    unsigned ucr  = h2u(__floats2half2_rn(cr,  cr));
    unsigned ucg  = h2u(__floats2half2_rn(cg,  cg));
    unsigned ucb  = h2u(__floats2half2_rn(cb,  cb));

    u64* q = g_tab + (size_t)m * SLOTS;
    q[0] = ((u64)ur12 << 32) | ur11;   // {r11, r12}
    q[1] = ((u64)um1  << 32) | ur22;   // {r22, m1 }
    q[2] = ((u64)ucr  << 32) | um2;    // {m2,  cr }
    q[3] = ((u64)ucb  << 32) | ucg;    // {cg,  cb }
}

// ---- Main render ----
__global__ __launch_bounds__(BLK, 1)
void render_kernel(const float* __restrict__ x, float* __restrict__ out)
{
    extern __shared__ u64 sh[];
    const int tid = threadIdx.x;

    // bulk copy table into shared
    {
        const ulonglong2* src = (const ulonglong2*)g_tab;
        ulonglong2* dst = (ulonglong2*)sh;
        #pragma unroll 4
        for (int i = tid; i < N_GAUSS * SLOTS / 2; i += BLK) dst[i] = src[i];
    }
    __syncthreads();

    const int slice = tid >> 6;                   // 0..7, 2 warps per slice
    const int slot  = tid & (SPB - 1);            // 0..63
    const int sg    = blockIdx.x + GRID * slot;   // round-robin pair-slot
    const bool active = (sg < NSLOT);

    __half2 Xh[P], Yh[P];                         // {x_pix0, x_pix1} per pair
    float aR0[P], aR1[P], aG0[P], aG1[P], aB0[P], aB1[P];

    if (active) {
        #pragma unroll
        for (int i = 0; i < P; ++i) {
            float4 xv = ((const float4*)x)[sg + NSLOT * i];
            Xh[i] = __floats2half2_rn(xv.x, xv.z);
            Yh[i] = __floats2half2_rn(xv.y, xv.w);
            aR0[i] = aR1[i] = aG0[i] = aG1[i] = aB0[i] = aB1[i] = 0.f;
        }

        const ulonglong2* S = (const ulonglong2*)sh;   // 2 x LDS.128 per Gaussian
        const int mbase = slice * GQ;

        for (int blk = 0; blk < GQ / 8; ++blk) {
            __half2 hR[P], hG[P], hB[P];
            #pragma unroll
            for (int i = 0; i < P; ++i) {
                hR[i] = u2h(0u); hG[i] = u2h(0u); hB[i] = u2h(0u);
            }

            #pragma unroll
            for (int j = 0; j < 8; ++j) {
                const int m = mbase + blk * 8 + j;
                ulonglong2 v0 = S[m * 2 + 0];
                ulonglong2 v1 = S[m * 2 + 1];
                __half2 r11 = u2h((unsigned)v0.x);
                __half2 r12 = u2h((unsigned)(v0.x >> 32));
                __half2 r22 = u2h((unsigned)v0.y);
                __half2 m1  = u2h((unsigned)(v0.y >> 32));
                __half2 m2  = u2h((unsigned)v1.x);
                __half2 cr  = u2h((unsigned)(v1.x >> 32));
                __half2 cg  = u2h((unsigned)v1.y);
                __half2 cb  = u2h((unsigned)(v1.y >> 32));

                #pragma unroll
                for (int i = 0; i < P; ++i) {
                    // e1 = r11*x + r12*y + m1 ; e2 = r22*y + m2
                    __half2 e1 = __hfma2(r11, Xh[i], __hfma2(r12, Yh[i], m1));
                    __half2 e2 = __hfma2(r22, Yh[i], m2);
                    // tp = e1^2 + e2^2 ; t = -tp (XOR sign bits, alu pipe)
                    __half2 tp = __hfma2(e2, e2, __hmul2(e1, e1));
                    __half2 w  = u2h(ex2_h2(h2u(tp) ^ 0x80008000u));
                    hR[i] = __hfma2(cr, w, hR[i]);
                    hG[i] = __hfma2(cg, w, hG[i]);
                    hB[i] = __hfma2(cb, w, hB[i]);
                }
            }
            #pragma unroll
            for (int i = 0; i < P; ++i) {
                float2 fr = __half22float2(hR[i]); aR0[i] += fr.x; aR1[i] += fr.y;
                float2 fg = __half22float2(hG[i]); aG0[i] += fg.x; aG1[i] += fg.y;
                float2 fb = __half22float2(hB[i]); aB0[i] += fb.x; aB1[i] += fb.y;
            }
        }
    }

    // ---- cross-slice reduction via shared (reuse table region) ----
    __syncthreads();                  // all reads of S done
    float* red = (float*)sh;          // [Q-1][SPB][P][6] = 43KB < 64KB
    if (slice != 0 && active) {
        float* qp = red + (((slice - 1) * SPB + slot) * P) * 6;
        #pragma unroll
        for (int i = 0; i < P; ++i) {
            float* qq = qp + i * 6;
            qq[0] = aR0[i]; qq[1] = aR1[i];
            qq[2] = aG0[i]; qq[3] = aG1[i];
            qq[4] = aB0[i]; qq[5] = aB1[i];
        }
    }
    __syncthreads();
    if (slice == 0 && active) {
        #pragma unroll
        for (int i = 0; i < P; ++i) {
            float r0 = aR0[i], r1 = aR1[i];
            float g0 = aG0[i], g1 = aG1[i];
            float b0 = aB0[i], b1 = aB1[i];
            for (int qd = 0; qd < Q - 1; ++qd) {
                const float* qq = red + (((qd * SPB + slot) * P) + i) * 6;
                r0 += qq[0]; r1 += qq[1];
                g0 += qq[2]; g1 += qq[3];
                b0 += qq[4]; b1 += qq[5];
            }
            const int p = sg + NSLOT * i;        // pair index
            float2* o = (float2*)(out + (size_t)p * 6);
            o[0] = make_float2(r0, g0);
            o[1] = make_float2(b0, r1);
            o[2] = make_float2(g1, b1);
        }
    }
}

extern "C" void kernel_launch(void* const* d_in, const int* in_sizes, int n_in,
                              void* d_out, int out_size)
{
    const float* x    = (const float*)d_in[0];
    const float* mus  = (const float*)d_in[1];
    const float* covs = (const float*)d_in[2];
    const float* cols = (const float*)d_in[3];
    float* out = (float*)d_out;

    prep_kernel<<<(N_GAUSS + 255) / 256, 256>>>(mus, covs, cols);

    cudaFuncSetAttribute(render_kernel,
                         cudaFuncAttributeMaxDynamicSharedMemorySize,
                         (int)SMEM_BYTES);
    render_kernel<<<GRID, BLK, SMEM_BYTES>>>(x, out);
}

// round 12
// speedup vs baseline: 2.0255x; 1.2655x over previous
#include <cuda_runtime.h>
#include <cuda_fp16.h>

// Gaussian-splat render, round 9: HMMA color accumulation.
//   out[n,c] = sum_m exp(-0.5 * d^T C_m^-1 d) * cols[m,c]
//
// R8 (47.6us) is fma-pipe-work bound (8 HFMA2 per pair-G, fma=74%).
// R9 moves the color sum (3 of 8 ops) onto the tensor pipe:
//   out = W @ cols  via  mma.sync.m16n8k16 (f16 x f16 -> f32 accum).
// The Cholesky quadratic eval (5 HFMA2 + ex2.f16x2) computes W directly in
// the mma A-fragment layout: eval half2 = (one pixel, two Gaussians), so
// coefficients are packed {g_even, g_odd} instead of lane-duplicated.
//
// Layout per warp: tile = 16 pix x 16 G, x4 M-tiles = 64 pixels.
// CTA: 16 warps = 16 G-slices (128 G = 8 chunks each), all on one
// 64-pixel group per round; 1024 groups, 7 rounds of group = bid + 148*r.
// Reduction: per-slice smem slabs + 192-thread sum -> contiguous STG.

typedef unsigned long long u64;

static constexpr int N_GAUSS  = 2048;
static constexpr int N_CHUNK  = 128;    // 16 Gaussians per chunk
static constexpr int N_GROUP  = 1024;   // 64 pixels per group
static constexpr int BLK      = 512;    // 16 warps = 16 slices
static constexpr int GRID     = 148;
static constexpr int ROUNDS   = 7;      // ceil(1024/148)

// combined table: coeffs [128][8][5] u32 then bfrag [128][32][2] u32
static constexpr int COEF_U32  = N_CHUNK * 8 * 5;    // 5120
static constexpr int BFRAG_U32 = N_CHUNK * 32 * 2;   // 8192
static constexpr int TAB_U32   = COEF_U32 + BFRAG_U32; // 13312
static constexpr size_t SMEM_BYTES = TAB_U32 * 4 + 16 * 192 * 4; // 65536

__device__ unsigned g_tab2[TAB_U32];

__device__ __forceinline__ unsigned h2u(__half2 h) {
    return *reinterpret_cast<unsigned*>(&h);
}
__device__ __forceinline__ __half2 u2h(unsigned u) {
    return *reinterpret_cast<__half2*>(&u);
}
__device__ __forceinline__ unsigned ex2_h2(unsigned v) {
    unsigned r; asm("ex2.approx.f16x2 %0, %1;" : "=r"(r) : "r"(v)); return r;
}

// ---- Prep: Cholesky coeff pairs + mma B-fragment color table ----
__global__ void prep_kernel(const float* __restrict__ mus,
                            const float* __restrict__ covs,
                            const float* __restrict__ cols)
{
    int idx = blockIdx.x * blockDim.x + threadIdx.x;

    // B-fragments: one thread per (chunk, lane)
    if (idx < N_CHUNK * 32) {
        int chunk = idx >> 5, t = idx & 31;
        int c  = t >> 2;              // mma column = color index (0..7)
        int p0 = t & 3, p1 = (t & 3) + 4;
        int gA0 = chunk * 16 + 2 * p0, gA1 = gA0 + 1;
        int gB0 = chunk * 16 + 2 * p1, gB1 = gB0 + 1;
        float b00 = (c < 3) ? cols[gA0 * 3 + c] : 0.f;
        float b01 = (c < 3) ? cols[gA1 * 3 + c] : 0.f;
        float b10 = (c < 3) ? cols[gB0 * 3 + c] : 0.f;
        float b11 = (c < 3) ? cols[gB1 * 3 + c] : 0.f;
        g_tab2[COEF_U32 + chunk * 64 + t * 2 + 0] = h2u(__floats2half2_rn(b00, b01));
        g_tab2[COEF_U32 + chunk * 64 + t * 2 + 1] = h2u(__floats2half2_rn(b10, b11));
    }

    // coefficient pairs: one thread per G-pair (1024)
    if (idx < N_GAUSS / 2) {
        int chunk = idx >> 3, p = idx & 7;
        float v[2][5];
        #pragma unroll
        for (int h = 0; h < 2; ++h) {
            int m = chunk * 16 + 2 * p + h;
            const float k = 0.72134752044448170368f;   // 0.5 * log2(e)
            float2 mu = ((const float2*)mus)[m];
            float4 cv = ((const float4*)covs)[m];      // [a, b, b, c]
            float a = cv.x, b = cv.y, c = cv.w;
            float inv_det = 1.0f / (a * c - b * b);
            float p00 =  c * inv_det * k;
            float p01 = -b * inv_det * k;
            float p11 =  a * inv_det * k;
            float r11 = sqrtf(p00);
            float r12 = p01 / r11;
            float r22 = sqrtf(fmaxf(p11 - r12 * r12, 0.f));
            v[h][0] = r11;
            v[h][1] = r12;
            v[h][2] = r22;
            v[h][3] = -(r11 * mu.x + r12 * mu.y);
            v[h][4] = -(r22 * mu.y);
        }
        #pragma unroll
        for (int c = 0; c < 5; ++c)
            g_tab2[chunk * 40 + p * 5 + c] = h2u(__floats2half2_rn(v[0][c], v[1][c]));
    }
}

// quadratic eval -> fp16x2 weight for (one pixel, two Gaussians)
__device__ __forceinline__ unsigned evalw(__half2 X, __half2 Y,
                                          __half2 r11, __half2 r12, __half2 r22,
                                          __half2 m1, __half2 m2)
{
    __half2 e1 = __hfma2(r11, X, __hfma2(r12, Y, m1));
    __half2 e2 = __hfma2(r22, Y, m2);
    __half2 tp = __hfma2(e2, e2, __hmul2(e1, e1));
    return ex2_h2(h2u(tp) ^ 0x80008000u);     // exp2(-(e1^2+e2^2))
}

__device__ __forceinline__ void mma16816(float& d0, float& d1, float& d2, float& d3,
                                         unsigned a0, unsigned a1, unsigned a2, unsigned a3,
                                         unsigned b0, unsigned b1)
{
    asm("mma.sync.aligned.m16n8k16.row.col.f32.f16.f16.f32 "
        "{%0,%1,%2,%3}, {%4,%5,%6,%7}, {%8,%9}, {%0,%1,%2,%3};"
        : "+f"(d0), "+f"(d1), "+f"(d2), "+f"(d3)
        : "r"(a0), "r"(a1), "r"(a2), "r"(a3), "r"(b0), "r"(b1));
}

// ---- Main render ----
__global__ __launch_bounds__(BLK, 1)
void render_kernel(const float* __restrict__ x, float* __restrict__ out)
{
    extern __shared__ unsigned sh[];
    const int tid = threadIdx.x;
    const int wid = tid >> 5;              // warp = Gaussian slice (0..15)
    const int lane = tid & 31;
    const int qr = lane >> 2;              // fragment row base (0..7)
    const int qc = lane & 3;               // fragment col-pair group (0..3)

    // bulk copy tables into shared
    {
        const uint4* src = (const uint4*)g_tab2;
        uint4* dst = (uint4*)sh;
        #pragma unroll 2
        for (int i = tid; i < TAB_U32 / 4; i += BLK) dst[i] = src[i];
    }
    float* red = (float*)(sh + TAB_U32);   // [16][192]
    __syncthreads();

    for (int rnd = 0; rnd < ROUNDS; ++rnd) {
        const int group = blockIdx.x + GRID * rnd;
        const bool act = (group < N_GROUP);

        if (act) {
            // load this warp's 64 pixels: [mt][rowhalf] -> pixel 64g + 16mt + qr + 8h
            __half2 Xh[8], Yh[8];
            #pragma unroll
            for (int mt = 0; mt < 4; ++mt) {
                #pragma unroll
                for (int h = 0; h < 2; ++h) {
                    int pix = group * 64 + mt * 16 + qr + h * 8;
                    float2 v = ((const float2*)x)[pix];
                    Xh[mt * 2 + h] = __floats2half2_rn(v.x, v.x);
                    Yh[mt * 2 + h] = __floats2half2_rn(v.y, v.y);
                }
            }

            float d[4][4];
            #pragma unroll
            for (int mt = 0; mt < 4; ++mt)
                d[mt][0] = d[mt][1] = d[mt][2] = d[mt][3] = 0.f;

            #pragma unroll 2
            for (int j = 0; j < 8; ++j) {
                const int chunk = wid * 8 + j;
                const unsigned* cA = sh + chunk * 40 + qc * 5;       // pair qc
                const unsigned* cB = cA + 20;                        // pair qc+4
                __half2 Ar11 = u2h(cA[0]), Ar12 = u2h(cA[1]), Ar22 = u2h(cA[2]);
                __half2 Am1  = u2h(cA[3]), Am2  = u2h(cA[4]);
                __half2 Br11 = u2h(cB[0]), Br12 = u2h(cB[1]), Br22 = u2h(cB[2]);
                __half2 Bm1  = u2h(cB[3]), Bm2  = u2h(cB[4]);
                u64 bb = *(const u64*)(sh + COEF_U32 + chunk * 64 + lane * 2);
                unsigned b0 = (unsigned)bb, b1 = (unsigned)(bb >> 32);

                #pragma unroll
                for (int mt = 0; mt < 4; ++mt) {
                    unsigned a0 = evalw(Xh[2*mt],   Yh[2*mt],   Ar11, Ar12, Ar22, Am1, Am2);
                    unsigned a1 = evalw(Xh[2*mt+1], Yh[2*mt+1], Ar11, Ar12, Ar22, Am1, Am2);
                    unsigned a2 = evalw(Xh[2*mt],   Yh[2*mt],   Br11, Br12, Br22, Bm1, Bm2);
                    unsigned a3 = evalw(Xh[2*mt+1], Yh[2*mt+1], Br11, Br12, Br22, Bm1, Bm2);
                    mma16816(d[mt][0], d[mt][1], d[mt][2], d[mt][3],
                             a0, a1, a2, a3, b0, b1);
                }
            }

            // write this slice's partial rgb into its slab: red[wid][pix_in_grp*3 + c]
            float* rp = red + wid * 192;
            if (qc == 0) {          // cols 0,1 = R,G
                #pragma unroll
                for (int mt = 0; mt < 4; ++mt) {
                    int p0 = mt * 16 + qr, p1 = p0 + 8;
                    rp[p0 * 3 + 0] = d[mt][0];
                    rp[p0 * 3 + 1] = d[mt][1];
                    rp[p1 * 3 + 0] = d[mt][2];
                    rp[p1 * 3 + 1] = d[mt][3];
                }
            } else if (qc == 1) {   // col 2 = B (col 3 = pad)
                #pragma unroll
                for (int mt = 0; mt < 4; ++mt) {
                    int p0 = mt * 16 + qr, p1 = p0 + 8;
                    rp[p0 * 3 + 2] = d[mt][0];
                    rp[p1 * 3 + 2] = d[mt][2];
                }
            }
        }
        __syncthreads();

        if (act && tid < 192) {
            float s = 0.f;
            #pragma unroll
            for (int w = 0; w < 16; ++w) s += red[w * 192 + tid];
            out[group * 192 + tid] = s;
        }
        __syncthreads();
    }
}

extern "C" void kernel_launch(void* const* d_in, const int* in_sizes, int n_in,
                              void* d_out, int out_size)
{
    const float* x    = (const float*)d_in[0];
    const float* mus  = (const float*)d_in[1];
    const float* covs = (const float*)d_in[2];
    const float* cols = (const float*)d_in[3];
    float* out = (float*)d_out;

    prep_kernel<<<(N_CHUNK * 32 + 255) / 256, 256>>>(mus, covs, cols);

    cudaFuncSetAttribute(render_kernel,
                         cudaFuncAttributeMaxDynamicSharedMemorySize,
                         (int)SMEM_BYTES);
    render_kernel<<<GRID, BLK, SMEM_BYTES>>>(x, out);
}

// round 14
// speedup vs baseline: 2.1422x; 1.0576x over previous
#include <cuda_runtime.h>
#include <cuda_fp16.h>

// Gaussian-splat render, round 10: R9 structure + issue-efficiency pass.
//   out[n,c] = sum_m exp(-0.5 * d^T C_m^-1 d) * cols[m,c]
//
// R9 (37.6us): HMMA color accum; ideal pipe time ~19.6us, 53% efficiency.
// R10 changes (no structural change):
//  * Coeff repack: per (chunk,qc) the A/B pair coeffs are contiguous ->
//    2x LDS.128 + 1x LDS.64 per chunk (was 10x LDS.32 + LDS.64).
//  * Negation folded into HFMA2 source modifier (hneg2) - drops the LOP3.
//  * j-loop unroll x4 to overlap LDS latency across chunks.

typedef unsigned long long u64;

static constexpr int N_GAUSS  = 2048;
static constexpr int N_CHUNK  = 128;    // 16 Gaussians per chunk
static constexpr int N_GROUP  = 1024;   // 64 pixels per group
static constexpr int BLK      = 512;    // 16 warps = 16 slices
static constexpr int GRID     = 148;
static constexpr int ROUNDS   = 7;      // ceil(1024/148)

// coeffs: [128 chunks][4 qc][12 u32]  (A:r11,r12,r22,m1,m2 B:r11,r12,r22,m1,m2 +2 pad)
static constexpr int COEF_U32  = N_CHUNK * 4 * 12;   // 6144
static constexpr int BFRAG_U32 = N_CHUNK * 32 * 2;   // 8192
static constexpr int TAB_U32   = COEF_U32 + BFRAG_U32; // 14336
static constexpr size_t SMEM_BYTES = TAB_U32 * 4 + 16 * 192 * 4; // 69632

__device__ unsigned g_tab2[TAB_U32];

__device__ __forceinline__ unsigned h2u(__half2 h) {
    return *reinterpret_cast<unsigned*>(&h);
}
__device__ __forceinline__ __half2 u2h(unsigned u) {
    return *reinterpret_cast<__half2*>(&u);
}
__device__ __forceinline__ unsigned ex2_h2(unsigned v) {
    unsigned r; asm("ex2.approx.f16x2 %0, %1;" : "=r"(r) : "r"(v)); return r;
}

// ---- Prep: Cholesky coeff pairs (vector layout) + mma B-fragment colors ----
__global__ void prep_kernel(const float* __restrict__ mus,
                            const float* __restrict__ covs,
                            const float* __restrict__ cols)
{
    int idx = blockIdx.x * blockDim.x + threadIdx.x;

    // B-fragments: one thread per (chunk, lane)
    if (idx < N_CHUNK * 32) {
        int chunk = idx >> 5, t = idx & 31;
        int c  = t >> 2;              // mma column = color index (0..7)
        int p0 = t & 3, p1 = (t & 3) + 4;
        int gA0 = chunk * 16 + 2 * p0, gA1 = gA0 + 1;
        int gB0 = chunk * 16 + 2 * p1, gB1 = gB0 + 1;
        float b00 = (c < 3) ? cols[gA0 * 3 + c] : 0.f;
        float b01 = (c < 3) ? cols[gA1 * 3 + c] : 0.f;
        float b10 = (c < 3) ? cols[gB0 * 3 + c] : 0.f;
        float b11 = (c < 3) ? cols[gB1 * 3 + c] : 0.f;
        g_tab2[COEF_U32 + chunk * 64 + t * 2 + 0] = h2u(__floats2half2_rn(b00, b01));
        g_tab2[COEF_U32 + chunk * 64 + t * 2 + 1] = h2u(__floats2half2_rn(b10, b11));
    }

    // coefficient pairs: one thread per G-pair (1024)
    if (idx < N_GAUSS / 2) {
        int chunk = idx >> 3, p = idx & 7;
        int g = p & 3;
        bool isB = (p >= 4);
        float v[2][5];
        #pragma unroll
        for (int h = 0; h < 2; ++h) {
            int m = chunk * 16 + 2 * p + h;
            const float k = 0.72134752044448170368f;   // 0.5 * log2(e)
            float2 mu = ((const float2*)mus)[m];
            float4 cv = ((const float4*)covs)[m];      // [a, b, b, c]
            float a = cv.x, b = cv.y, c = cv.w;
            float inv_det = 1.0f / (a * c - b * b);
            float p00 =  c * inv_det * k;
            float p01 = -b * inv_det * k;
            float p11 =  a * inv_det * k;
            float r11 = sqrtf(p00);
            float r12 = p01 / r11;
            float r22 = sqrtf(fmaxf(p11 - r12 * r12, 0.f));
            v[h][0] = r11;
            v[h][1] = r12;
            v[h][2] = r22;
            v[h][3] = -(r11 * mu.x + r12 * mu.y);
            v[h][4] = -(r22 * mu.y);
        }
        // layout per (chunk,g): [A0 A1 A2 A3][A4 B0 B1 B2][B3 B4 pad pad]
        unsigned* base = g_tab2 + chunk * 48 + g * 12;
        #pragma unroll
        for (int c = 0; c < 5; ++c) {
            unsigned val = h2u(__floats2half2_rn(v[0][c], v[1][c]));
            base[(isB ? 5 : 0) + c] = val;
        }
        if (idx < N_CHUNK) {   // zero the pads once per chunk (threads p==0)
            // (not strictly needed; pads never read)
        }
    }
}

// quadratic eval -> fp16x2 weight exp2(-(e1^2+e2^2)) for (one pixel, two G)
__device__ __forceinline__ unsigned evalw(__half2 X, __half2 Y,
                                          __half2 r11, __half2 r12, __half2 r22,
                                          __half2 m1, __half2 m2)
{
    __half2 e1 = __hfma2(r11, X, __hfma2(r12, Y, m1));
    __half2 e2 = __hfma2(r22, Y, m2);
    __half2 tp = __hfma2(__hneg2(e2), e2, __hmul2(__hneg2(e1), e1));
    return ex2_h2(h2u(tp));
}

__device__ __forceinline__ void mma16816(float& d0, float& d1, float& d2, float& d3,
                                         unsigned a0, unsigned a1, unsigned a2, unsigned a3,
                                         unsigned b0, unsigned b1)
{
    asm("mma.sync.aligned.m16n8k16.row.col.f32.f16.f16.f32 "
        "{%0,%1,%2,%3}, {%4,%5,%6,%7}, {%8,%9}, {%0,%1,%2,%3};"
        : "+f"(d0), "+f"(d1), "+f"(d2), "+f"(d3)
        : "r"(a0), "r"(a1), "r"(a2), "r"(a3), "r"(b0), "r"(b1));
}

// ---- Main render ----
__global__ __launch_bounds__(BLK, 1)
void render_kernel(const float* __restrict__ x, float* __restrict__ out)
{
    extern __shared__ unsigned sh[];
    const int tid = threadIdx.x;
    const int wid = tid >> 5;              // warp = Gaussian slice (0..15)
    const int lane = tid & 31;
    const int qr = lane >> 2;              // fragment row base (0..7)
    const int qc = lane & 3;               // fragment col-pair group (0..3)

    // bulk copy tables into shared
    {
        const uint4* src = (const uint4*)g_tab2;
        uint4* dst = (uint4*)sh;
        #pragma unroll 2
        for (int i = tid; i < TAB_U32 / 4; i += BLK) dst[i] = src[i];
    }
    float* red = (float*)(sh + TAB_U32);   // [16][192]
    __syncthreads();

    for (int rnd = 0; rnd < ROUNDS; ++rnd) {
        const int group = blockIdx.x + GRID * rnd;
        const bool act = (group < N_GROUP);

        if (act) {
            // this warp's 64 pixels: [mt][rowhalf] -> pixel 64g + 16mt + qr + 8h
            __half2 Xh[8], Yh[8];
            #pragma unroll
            for (int mt = 0; mt < 4; ++mt) {
                #pragma unroll
                for (int h = 0; h < 2; ++h) {
                    int pix = group * 64 + mt * 16 + qr + h * 8;
                    float2 v = ((const float2*)x)[pix];
                    Xh[mt * 2 + h] = __floats2half2_rn(v.x, v.x);
                    Yh[mt * 2 + h] = __floats2half2_rn(v.y, v.y);
                }
            }

            float d[4][4];
            #pragma unroll
            for (int mt = 0; mt < 4; ++mt)
                d[mt][0] = d[mt][1] = d[mt][2] = d[mt][3] = 0.f;

            #pragma unroll 4
            for (int j = 0; j < 8; ++j) {
                const int chunk = wid * 8 + j;
                const unsigned* cp = sh + chunk * 48 + qc * 12;
                uint4 w0 = *(const uint4*)(cp);        // A r11 r12 r22 m1
                uint4 w1 = *(const uint4*)(cp + 4);    // A m2 | B r11 r12 r22
                u64  w2 = *(const u64*)(cp + 8);       // B m1 m2
                __half2 Ar11 = u2h(w0.x), Ar12 = u2h(w0.y), Ar22 = u2h(w0.z);
                __half2 Am1  = u2h(w0.w), Am2  = u2h(w1.x);
                __half2 Br11 = u2h(w1.y), Br12 = u2h(w1.z), Br22 = u2h(w1.w);
                __half2 Bm1  = u2h((unsigned)w2), Bm2 = u2h((unsigned)(w2 >> 32));

                u64 bb = *(const u64*)(sh + COEF_U32 + chunk * 64 + lane * 2);
                unsigned b0 = (unsigned)bb, b1 = (unsigned)(bb >> 32);

                #pragma unroll
                for (int mt = 0; mt < 4; ++mt) {
                    unsigned a0 = evalw(Xh[2*mt],   Yh[2*mt],   Ar11, Ar12, Ar22, Am1, Am2);
                    unsigned a1 = evalw(Xh[2*mt+1], Yh[2*mt+1], Ar11, Ar12, Ar22, Am1, Am2);
                    unsigned a2 = evalw(Xh[2*mt],   Yh[2*mt],   Br11, Br12, Br22, Bm1, Bm2);
                    unsigned a3 = evalw(Xh[2*mt+1], Yh[2*mt+1], Br11, Br12, Br22, Bm1, Bm2);
                    mma16816(d[mt][0], d[mt][1], d[mt][2], d[mt][3],
                             a0, a1, a2, a3, b0, b1);
                }
            }

            // write this slice's partial rgb: red[wid][pix_in_grp*3 + c]
            float* rp = red + wid * 192;
            if (qc == 0) {          // cols 0,1 = R,G
                #pragma unroll
                for (int mt = 0; mt < 4; ++mt) {
                    int p0 = mt * 16 + qr, p1 = p0 + 8;
                    rp[p0 * 3 + 0] = d[mt][0];
                    rp[p0 * 3 + 1] = d[mt][1];
                    rp[p1 * 3 + 0] = d[mt][2];
                    rp[p1 * 3 + 1] = d[mt][3];
                }
            } else if (qc == 1) {   // col 2 = B
                #pragma unroll
                for (int mt = 0; mt < 4; ++mt) {
                    int p0 = mt * 16 + qr, p1 = p0 + 8;
                    rp[p0 * 3 + 2] = d[mt][0];
                    rp[p1 * 3 + 2] = d[mt][2];
                }
            }
        }
        __syncthreads();

        if (act && tid < 192) {
            float s = 0.f;
            #pragma unroll
            for (int w = 0; w < 16; ++w) s += red[w * 192 + tid];
            out[group * 192 + tid] = s;
        }
        __syncthreads();
    }
}

extern "C" void kernel_launch(void* const* d_in, const int* in_sizes, int n_in,
                              void* d_out, int out_size)
{
    const float* x    = (const float*)d_in[0];
    const float* mus  = (const float*)d_in[1];
    const float* covs = (const float*)d_in[2];
    const float* cols = (const float*)d_in[3];
    float* out = (float*)d_out;

    prep_kernel<<<(N_CHUNK * 32 + 255) / 256, 256>>>(mus, covs, cols);

    cudaFuncSetAttribute(render_kernel,
                         cudaFuncAttributeMaxDynamicSharedMemorySize,
                         (int)SMEM_BYTES);
    render_kernel<<<GRID, BLK, SMEM_BYTES>>>(x, out);
}